// round 2
// baseline (speedup 1.0000x reference)
#include <cuda_runtime.h>
#include <cstdint>

#define NN   50000
#define EE   1600000
#define ETOT (EE + NN)
#define HC   128
#define NH   2
#define NEG  0.2f
#define EPSV 1e-5f

// ---------------- scratch (device globals; no runtime allocation) ----------
__device__ float    g_xl[(size_t)NN * HC];     // x @ W_l   (25.6 MB)
__device__ float    g_xr[(size_t)NN * HC];     // x @ W_r   (25.6 MB)
__device__ float    g_elog[(size_t)ETOT * NH]; // per-edge logits -> exp (13.2 MB)
__device__ unsigned g_skey[NN * NH];           // segment max (ordered-uint keys)
__device__ float    g_smax[NN * NH];
__device__ float    g_ssum[NN * NH];
__device__ float    g_sinv[NN * NH];
__device__ float    g_chs1[HC];
__device__ float    g_chs2[HC];
__device__ float    g_WtL[HC * HC];            // W_l transposed [c][k]
__device__ float    g_WtR[HC * HC];
__device__ int      g_is64;

// ---------------- helpers ---------------------------------------------------
__device__ __forceinline__ unsigned fkey(float f) {
    unsigned b = __float_as_uint(f);
    return b ^ ((unsigned)((int)b >> 31) | 0x80000000u);
}
__device__ __forceinline__ float fkey_dec(unsigned k) {
    unsigned b = (k & 0x80000000u) ? (k ^ 0x80000000u) : ~k;
    return __uint_as_float(b);
}
__device__ __forceinline__ void load_edge(const void* ei, int e, int& src, int& dst) {
    if (e >= EE) { src = dst = e - EE; return; }
    if (g_is64) {
        const long long* p = (const long long*)ei;
        src = (int)p[e]; dst = (int)p[EE + e];
    } else {
        const int* p = (const int*)ei;
        src = p[e]; dst = p[EE + e];
    }
}

// ---------------- kernels ----------------------------------------------------

// detect int64 vs int32 edge_index: if int64 (little-endian, values < 2^31),
// every odd 32-bit word of the first entries is zero.
__global__ void k_detect(const void* ei) {
    if (threadIdx.x == 0) {
        const int* p = (const int*)ei;
        int is64 = 1;
        #pragma unroll 1
        for (int i = 0; i < 64; i++) {
            if (p[2 * i + 1] != 0) { is64 = 0; break; }
        }
        g_is64 = is64;
    }
}

__global__ void k_init(float* out) {
    int stride = gridDim.x * blockDim.x;
    for (size_t i = blockIdx.x * blockDim.x + threadIdx.x; i < (size_t)NN * HC; i += stride) {
        out[i] = 0.0f;
        if (i < NN * NH) { g_skey[i] = 0u; g_ssum[i] = 0.0f; }
        if (i < HC)      { g_chs1[i] = 0.0f; g_chs2[i] = 0.0f; }
    }
}

__global__ void k_transpose(const float* __restrict__ Wl, const float* __restrict__ Wr) {
    int i = blockIdx.x * blockDim.x + threadIdx.x;
    if (i >= HC * HC) return;
    int k = i >> 7, c = i & 127;
    g_WtL[c * HC + k] = Wl[i];
    g_WtR[c * HC + k] = Wr[i];
}

// fp32 GEMM: 32 nodes per block, 128 threads (thread = output column).
__global__ __launch_bounds__(128) void k_gemm(const float* __restrict__ x) {
    __shared__ float4 xs[32][32];           // [row][k4] 16 KB
    const int node0 = blockIdx.x * 32;
    const int c = threadIdx.x;

    // load x tile (32 x 128 floats = 1024 float4)
    const float4* x4 = (const float4*)x;
    #pragma unroll
    for (int i = 0; i < 8; i++) {
        int lin = threadIdx.x + i * 128;
        int row = lin >> 5, k4 = lin & 31;
        int node = node0 + row;
        xs[row][k4] = (node < NN) ? x4[(size_t)node * 32 + k4]
                                  : make_float4(0.f, 0.f, 0.f, 0.f);
    }
    __syncthreads();

    float acc[32];
    const float4* wl = (const float4*)(g_WtL + c * HC);
    #pragma unroll
    for (int r = 0; r < 32; r++) acc[r] = 0.0f;
    #pragma unroll 4
    for (int k4 = 0; k4 < 32; k4++) {
        float4 w = wl[k4];
        #pragma unroll
        for (int r = 0; r < 32; r++) {
            float4 xv = xs[r][k4];
            acc[r] += xv.x * w.x + xv.y * w.y + xv.z * w.z + xv.w * w.w;
        }
    }
    #pragma unroll
    for (int r = 0; r < 32; r++) {
        int node = node0 + r;
        if (node < NN) g_xl[(size_t)node * HC + c] = acc[r];
    }

    const float4* wr = (const float4*)(g_WtR + c * HC);
    #pragma unroll
    for (int r = 0; r < 32; r++) acc[r] = 0.0f;
    #pragma unroll 4
    for (int k4 = 0; k4 < 32; k4++) {
        float4 w = wr[k4];
        #pragma unroll
        for (int r = 0; r < 32; r++) {
            float4 xv = xs[r][k4];
            acc[r] += xv.x * w.x + xv.y * w.y + xv.z * w.z + xv.w * w.w;
        }
    }
    #pragma unroll
    for (int r = 0; r < 32; r++) {
        int node = node0 + r;
        if (node < NN) g_xr[(size_t)node * HC + c] = acc[r];
    }
}

// pass A: one warp per edge -> logits + segment max (atomicMax on ordered keys)
__global__ __launch_bounds__(256) void k_logits(const void* __restrict__ ei,
                                                const float* __restrict__ att) {
    int e = (blockIdx.x * blockDim.x + threadIdx.x) >> 5;
    int lane = threadIdx.x & 31;
    if (e >= ETOT) return;
    int src, dst;
    load_edge(ei, e, src, dst);

    float4 a = *(const float4*)(g_xl + (size_t)src * HC + lane * 4);
    float4 b = *(const float4*)(g_xr + (size_t)dst * HC + lane * 4);
    float4 w = *(const float4*)(att + lane * 4);
    float sx = a.x + b.x, sy = a.y + b.y, sz = a.z + b.z, sw = a.w + b.w;
    sx = (sx > 0.f) ? sx : NEG * sx;
    sy = (sy > 0.f) ? sy : NEG * sy;
    sz = (sz > 0.f) ? sz : NEG * sz;
    sw = (sw > 0.f) ? sw : NEG * sw;
    float p = sx * w.x + sy * w.y + sz * w.z + sw * w.w;
    // reduce within each 16-lane half (head 0 = lanes 0..15, head 1 = 16..31)
    p += __shfl_xor_sync(0xffffffffu, p, 1);
    p += __shfl_xor_sync(0xffffffffu, p, 2);
    p += __shfl_xor_sync(0xffffffffu, p, 4);
    p += __shfl_xor_sync(0xffffffffu, p, 8);
    if (lane == 0) {
        g_elog[(size_t)e * 2 + 0] = p;
        atomicMax(&g_skey[dst * 2 + 0], fkey(p));
    }
    if (lane == 16) {
        g_elog[(size_t)e * 2 + 1] = p;
        atomicMax(&g_skey[dst * 2 + 1], fkey(p));
    }
}

__global__ void k_decode_max(void) {
    int i = blockIdx.x * blockDim.x + threadIdx.x;
    if (i < NN * NH) g_smax[i] = fkey_dec(g_skey[i]);
}

// pass B: exp(logit - max) and segment sum. one thread per (edge, head)
__global__ __launch_bounds__(256) void k_exp(const void* __restrict__ ei) {
    int idx = blockIdx.x * blockDim.x + threadIdx.x;
    if (idx >= ETOT * NH) return;
    int e = idx >> 1, h = idx & 1;
    int src, dst;
    load_edge(ei, e, src, dst);
    (void)src;
    float ex = __expf(g_elog[idx] - g_smax[dst * 2 + h]);
    g_elog[idx] = ex;
    atomicAdd(&g_ssum[dst * 2 + h], ex);
}

__global__ void k_inv(void) {
    int i = blockIdx.x * blockDim.x + threadIdx.x;
    if (i < NN * NH) g_sinv[i] = 1.0f / g_ssum[i];
}

// pass C: one warp per edge, vector float4 atomic scatter into out
__global__ __launch_bounds__(256) void k_aggregate(const void* __restrict__ ei,
                                                   float* __restrict__ out) {
    int e = (blockIdx.x * blockDim.x + threadIdx.x) >> 5;
    int lane = threadIdx.x & 31;
    if (e >= ETOT) return;
    int src, dst;
    load_edge(ei, e, src, dst);
    int h = lane >> 4;
    float alpha = g_elog[(size_t)e * 2 + h] * g_sinv[dst * 2 + h];
    float4 a = *(const float4*)(g_xl + (size_t)src * HC + lane * 4);
    float4 m = make_float4(alpha * a.x, alpha * a.y, alpha * a.z, alpha * a.w);
    atomicAdd((float4*)(out + (size_t)dst * HC + lane * 4), m);
}

// stats: thread = channel; block strides over node rows
__global__ __launch_bounds__(128) void k_stats(const float* __restrict__ out,
                                               const float* __restrict__ bias) {
    int c = threadIdx.x;
    float b = bias[c];
    float s1 = 0.f, s2 = 0.f;
    for (int i = blockIdx.x; i < NN; i += gridDim.x) {
        float v = out[(size_t)i * HC + c] + b;
        s1 += v;
        s2 += v * v;
    }
    atomicAdd(&g_chs1[c], s1);
    atomicAdd(&g_chs2[c], s2);
}

__global__ void k_norm(float* __restrict__ out,
                       const float* __restrict__ bias,
                       const float* __restrict__ gw,
                       const float* __restrict__ gb,
                       const float* __restrict__ gms) {
    const float invn = 1.0f / (float)NN;
    int stride = gridDim.x * blockDim.x;
    for (size_t i = blockIdx.x * blockDim.x + threadIdx.x; i < (size_t)NN * HC; i += stride) {
        int c = (int)(i & 127);
        float mean = g_chs1[c] * invn;
        float m2   = g_chs2[c] * invn;
        float ms   = mean * gms[c];
        float var  = m2 - 2.0f * ms * mean + ms * ms;
        float v = out[i] + bias[c];
        out[i] = gw[c] * (v - ms) * rsqrtf(var + EPSV) + gb[c];
    }
}

// ---------------- launch ------------------------------------------------------
extern "C" void kernel_launch(void* const* d_in, const int* in_sizes, int n_in,
                              void* d_out, int out_size) {
    const float* x    = (const float*)d_in[0];
    const void*  ei   = d_in[1];
    const float* Wl   = (const float*)d_in[2];
    const float* Wr   = (const float*)d_in[3];
    const float* att  = (const float*)d_in[4];
    const float* bias = (const float*)d_in[5];
    const float* gw   = (const float*)d_in[6];
    const float* gb   = (const float*)d_in[7];
    const float* gms  = (const float*)d_in[8];
    float* out = (float*)d_out;

    k_detect<<<1, 32>>>(ei);
    k_init<<<4096, 256>>>(out);
    k_transpose<<<(HC * HC + 255) / 256, 256>>>(Wl, Wr);
    k_gemm<<<(NN + 31) / 32, 128>>>(x);

    int eblocks = (ETOT + 7) / 8;  // 8 warps / 256-thread block
    k_logits<<<eblocks, 256>>>(ei, att);
    k_decode_max<<<(NN * NH + 255) / 256, 256>>>();
    k_exp<<<(ETOT * NH + 255) / 256, 256>>>(ei);
    k_inv<<<(NN * NH + 255) / 256, 256>>>();
    k_aggregate<<<eblocks, 256>>>(ei, out);

    k_stats<<<512, 128>>>(out, bias);
    k_norm<<<4096, 256>>>(out, bias, gw, gb, gms);
}

// round 5
// speedup vs baseline: 1.2803x; 1.2803x over previous
#include <cuda_runtime.h>
#include <cstdint>
#include <math_constants.h>

#define NN   50000
#define EE   1600000
#define ETOT (EE + NN)
#define HC   128
#define NH   2
#define NEG  0.2f
#define EPSV 1e-5f

// ---------------- scratch (device globals; no runtime allocation) ----------
__device__ float    g_xl[(size_t)NN * HC];      // x @ W_l   (25.6 MB)
__device__ float    g_xr[(size_t)NN * HC];      // x @ W_r   (25.6 MB)
__device__ float    g_elog[(size_t)ETOT * NH];  // per-edge logits (13.2 MB)
__device__ int      g_esrc[ETOT];               // CSR src array (6.6 MB)
__device__ int      g_deg[NN];
__device__ int      g_off[NN + 1];
__device__ int      g_cursor[NN];
__device__ float    g_m[NN * NH];               // per-node per-head max
__device__ float    g_sinv[NN * NH];            // per-node per-head 1/sum
__device__ float    g_chs1[HC];
__device__ float    g_chs2[HC];
__device__ int      g_is64;

// ---------------- helpers ---------------------------------------------------
__device__ __forceinline__ void load_edge(const void* ei, int e, int& src, int& dst) {
    if (e >= EE) { src = dst = e - EE; return; }
    if (g_is64) {
        const long long* p = (const long long*)ei;
        src = (int)p[e]; dst = (int)p[EE + e];
    } else {
        const int* p = (const int*)ei;
        src = p[e]; dst = p[EE + e];
    }
}

// ---------------- kernels ----------------------------------------------------

// detect int64 vs int32 edge_index (int64 little-endian values < 2^31 have
// zero odd words)
__global__ void k_detect(const void* ei) {
    if (threadIdx.x == 0) {
        const int* p = (const int*)ei;
        int is64 = 1;
        #pragma unroll 1
        for (int i = 0; i < 64; i++)
            if (p[2 * i + 1] != 0) { is64 = 0; break; }
        g_is64 = is64;
    }
}

__global__ void k_zero(void) {
    int i = blockIdx.x * blockDim.x + threadIdx.x;
    if (i < NN) g_deg[i] = 0;
    if (i < HC) { g_chs1[i] = 0.0f; g_chs2[i] = 0.0f; }
}

// fp32 GEMM: 64 nodes per block, 128 threads (thread = output column).
// W read in native [k][c] layout -> warp-coalesced loads.
__global__ __launch_bounds__(128) void k_gemm(const float* __restrict__ x,
                                              const float* __restrict__ Wl,
                                              const float* __restrict__ Wr) {
    __shared__ float4 xs[64][32];           // 32 KB
    const int node0 = blockIdx.x * 64;
    const int c = threadIdx.x;

    const float4* x4 = (const float4*)x;
    #pragma unroll
    for (int i = 0; i < 16; i++) {
        int lin = threadIdx.x + i * 128;
        int row = lin >> 5, k4 = lin & 31;
        int node = node0 + row;
        xs[row][k4] = (node < NN) ? x4[(size_t)node * 32 + k4]
                                  : make_float4(0.f, 0.f, 0.f, 0.f);
    }
    __syncthreads();

    float acc[64];
    #pragma unroll
    for (int r = 0; r < 64; r++) acc[r] = 0.0f;
    #pragma unroll 2
    for (int k4 = 0; k4 < 32; k4++) {
        float w0 = Wl[(k4 * 4 + 0) * HC + c];
        float w1 = Wl[(k4 * 4 + 1) * HC + c];
        float w2 = Wl[(k4 * 4 + 2) * HC + c];
        float w3 = Wl[(k4 * 4 + 3) * HC + c];
        #pragma unroll
        for (int r = 0; r < 64; r++) {
            float4 xv = xs[r][k4];
            acc[r] += xv.x * w0 + xv.y * w1 + xv.z * w2 + xv.w * w3;
        }
    }
    #pragma unroll
    for (int r = 0; r < 64; r++) {
        int node = node0 + r;
        if (node < NN) g_xl[(size_t)node * HC + c] = acc[r];
    }

    #pragma unroll
    for (int r = 0; r < 64; r++) acc[r] = 0.0f;
    #pragma unroll 2
    for (int k4 = 0; k4 < 32; k4++) {
        float w0 = Wr[(k4 * 4 + 0) * HC + c];
        float w1 = Wr[(k4 * 4 + 1) * HC + c];
        float w2 = Wr[(k4 * 4 + 2) * HC + c];
        float w3 = Wr[(k4 * 4 + 3) * HC + c];
        #pragma unroll
        for (int r = 0; r < 64; r++) {
            float4 xv = xs[r][k4];
            acc[r] += xv.x * w0 + xv.y * w1 + xv.z * w2 + xv.w * w3;
        }
    }
    #pragma unroll
    for (int r = 0; r < 64; r++) {
        int node = node0 + r;
        if (node < NN) g_xr[(size_t)node * HC + c] = acc[r];
    }
}

// CSR build step 1: degree histogram
__global__ __launch_bounds__(256) void k_hist(const void* __restrict__ ei) {
    int e = blockIdx.x * blockDim.x + threadIdx.x;
    if (e >= ETOT) return;
    int src, dst;
    load_edge(ei, e, src, dst);
    (void)src;
    atomicAdd(&g_deg[dst], 1);
}

// CSR build step 2: single-block exclusive scan over degrees
__global__ __launch_bounds__(1024) void k_scan(void) {
    __shared__ int ssum[1024];
    const int C = (NN + 1023) / 1024;  // 49
    int t = threadIdx.x;
    int lo = t * C, hi = min(lo + C, NN);
    int s = 0;
    for (int i = lo; i < hi; i++) s += g_deg[i];
    ssum[t] = s;
    __syncthreads();
    // Hillis-Steele inclusive scan
    for (int off = 1; off < 1024; off <<= 1) {
        int v = (t >= off) ? ssum[t - off] : 0;
        __syncthreads();
        ssum[t] += v;
        __syncthreads();
    }
    int excl = (t == 0) ? 0 : ssum[t - 1];
    for (int i = lo; i < hi; i++) {
        g_off[i] = excl;
        g_cursor[i] = excl;
        excl += g_deg[i];
    }
    if (t == 1023) g_off[NN] = ssum[1023];
}

// CSR build step 3: scatter srcs grouped by dst
__global__ __launch_bounds__(256) void k_scatter(const void* __restrict__ ei) {
    int e = blockIdx.x * blockDim.x + threadIdx.x;
    if (e >= ETOT) return;
    int src, dst;
    load_edge(ei, e, src, dst);
    int pos = atomicAdd(&g_cursor[dst], 1);
    g_esrc[pos] = src;
}

// pass 1: warp per node. logits + exact online softmax stats (no atomics).
__global__ __launch_bounds__(256) void k_edge1(const float* __restrict__ att) {
    int n = (blockIdx.x * blockDim.x + threadIdx.x) >> 5;
    int lane = threadIdx.x & 31;
    if (n >= NN) return;
    int base = g_off[n];
    int deg = g_off[n + 1] - base;

    float4 b = *(const float4*)(g_xr + (size_t)n * HC + lane * 4);
    float4 w = *(const float4*)(att + lane * 4);

    float m = -CUDART_INF_F, s = 0.0f;
    int src = g_esrc[base];
    for (int i = 0; i < deg; i++) {
        float4 a = *(const float4*)(g_xl + (size_t)src * HC + lane * 4);
        int nsrc = (i + 1 < deg) ? g_esrc[base + i + 1] : 0;
        float sx = a.x + b.x, sy = a.y + b.y, sz = a.z + b.z, sw = a.w + b.w;
        sx = (sx > 0.f) ? sx : NEG * sx;
        sy = (sy > 0.f) ? sy : NEG * sy;
        sz = (sz > 0.f) ? sz : NEG * sz;
        sw = (sw > 0.f) ? sw : NEG * sw;
        float p = sx * w.x + sy * w.y + sz * w.z + sw * w.w;
        p += __shfl_xor_sync(0xffffffffu, p, 1);
        p += __shfl_xor_sync(0xffffffffu, p, 2);
        p += __shfl_xor_sync(0xffffffffu, p, 4);
        p += __shfl_xor_sync(0xffffffffu, p, 8);
        // p now holds the head logit for this half-warp
        if (lane == 0)  g_elog[(size_t)(base + i) * 2 + 0] = p;
        if (lane == 16) g_elog[(size_t)(base + i) * 2 + 1] = p;
        float mn = fmaxf(m, p);
        s = s * __expf(m - mn) + __expf(p - mn);
        m = mn;
        src = nsrc;
    }
    if (lane == 0)  { g_m[n * 2 + 0] = m; g_sinv[n * 2 + 0] = 1.0f / s; }
    if (lane == 16) { g_m[n * 2 + 1] = m; g_sinv[n * 2 + 1] = 1.0f / s; }
}

// pass 2: warp per node. aggregate into registers, single store, no atomics.
__global__ __launch_bounds__(256) void k_edge2(float* __restrict__ out) {
    int n = (blockIdx.x * blockDim.x + threadIdx.x) >> 5;
    int lane = threadIdx.x & 31;
    if (n >= NN) return;
    int h = lane >> 4;
    int base = g_off[n];
    int deg = g_off[n + 1] - base;
    float m = g_m[n * 2 + h];
    float si = g_sinv[n * 2 + h];

    float4 acc = make_float4(0.f, 0.f, 0.f, 0.f);
    int src = g_esrc[base];
    for (int i = 0; i < deg; i++) {
        float4 a = *(const float4*)(g_xl + (size_t)src * HC + lane * 4);
        int nsrc = (i + 1 < deg) ? g_esrc[base + i + 1] : 0;
        float p = g_elog[(size_t)(base + i) * 2 + h];
        float alpha = __expf(p - m) * si;
        acc.x += alpha * a.x;
        acc.y += alpha * a.y;
        acc.z += alpha * a.z;
        acc.w += alpha * a.w;
        src = nsrc;
    }
    *(float4*)(out + (size_t)n * HC + lane * 4) = acc;
}

// stats: thread = channel; block strides over node rows
__global__ __launch_bounds__(128) void k_stats(const float* __restrict__ out,
                                               const float* __restrict__ bias) {
    int c = threadIdx.x;
    float b = bias[c];
    float s1 = 0.f, s2 = 0.f;
    for (int i = blockIdx.x; i < NN; i += gridDim.x) {
        float v = out[(size_t)i * HC + c] + b;
        s1 += v;
        s2 += v * v;
    }
    atomicAdd(&g_chs1[c], s1);
    atomicAdd(&g_chs2[c], s2);
}

__global__ void k_norm(float* __restrict__ out,
                       const float* __restrict__ bias,
                       const float* __restrict__ gw,
                       const float* __restrict__ gb,
                       const float* __restrict__ gms) {
    const float invn = 1.0f / (float)NN;
    int stride = gridDim.x * blockDim.x;
    for (size_t i = blockIdx.x * blockDim.x + threadIdx.x; i < (size_t)NN * HC; i += stride) {
        int c = (int)(i & 127);
        float mean = g_chs1[c] * invn;
        float m2   = g_chs2[c] * invn;
        float ms   = mean * gms[c];
        float var  = m2 - 2.0f * ms * mean + ms * ms;
        float v = out[i] + bias[c];
        out[i] = gw[c] * (v - ms) * rsqrtf(var + EPSV) + gb[c];
    }
}

// ---------------- launch ------------------------------------------------------
extern "C" void kernel_launch(void* const* d_in, const int* in_sizes, int n_in,
                              void* d_out, int out_size) {
    const float* x    = (const float*)d_in[0];
    const void*  ei   = d_in[1];
    const float* Wl   = (const float*)d_in[2];
    const float* Wr   = (const float*)d_in[3];
    const float* att  = (const float*)d_in[4];
    const float* bias = (const float*)d_in[5];
    const float* gw   = (const float*)d_in[6];
    const float* gb   = (const float*)d_in[7];
    const float* gms  = (const float*)d_in[8];
    float* out = (float*)d_out;

    k_detect<<<1, 32>>>(ei);
    k_zero<<<(NN + 255) / 256, 256>>>();
    k_gemm<<<(NN + 63) / 64, 128>>>(x, Wl, Wr);

    int eblk = (ETOT + 255) / 256;
    k_hist<<<eblk, 256>>>(ei);
    k_scan<<<1, 1024>>>();
    k_scatter<<<eblk, 256>>>(ei);

    int nblk = (NN * 32 + 255) / 256;  // warp per node
    k_edge1<<<nblk, 256>>>(att);
    k_edge2<<<nblk, 256>>>(out);

    k_stats<<<512, 128>>>(out, bias);
    k_norm<<<4096, 256>>>(out, bias, gw, gb, gms);
}

// round 6
// speedup vs baseline: 1.5366x; 1.2002x over previous
#include <cuda_runtime.h>
#include <cstdint>
#include <math_constants.h>

#define NN   50000
#define EE   1600000
#define ETOT (EE + NN)
#define HC   128
#define NH   2
#define NEG  0.2f
#define EPSV 1e-5f

// ---------------- scratch (device globals; no runtime allocation) ----------
__device__ float    g_xl[(size_t)NN * HC];      // x @ W_l   (25.6 MB)
__device__ float    g_xr[(size_t)NN * HC];      // x @ W_r   (25.6 MB)
__device__ int      g_esrc[ETOT];               // CSR src array (6.6 MB)
__device__ int      g_deg[NN];
__device__ int      g_off[NN + 1];
__device__ int      g_cursor[NN];
__device__ float    g_chs1[HC];
__device__ float    g_chs2[HC];
__device__ int      g_is64;

// ---------------- helpers ---------------------------------------------------
__device__ __forceinline__ void load_edge(const void* ei, int e, int& src, int& dst) {
    if (e >= EE) { src = dst = e - EE; return; }
    if (g_is64) {
        const long long* p = (const long long*)ei;
        src = (int)p[e]; dst = (int)p[EE + e];
    } else {
        const int* p = (const int*)ei;
        src = p[e]; dst = p[EE + e];
    }
}

// ---------------- kernels ----------------------------------------------------

// detect int64 vs int32 edge_index (int64 little-endian values < 2^31 have
// zero odd words)
__global__ void k_detect(const void* ei) {
    if (threadIdx.x == 0) {
        const int* p = (const int*)ei;
        int is64 = 1;
        #pragma unroll 1
        for (int i = 0; i < 64; i++)
            if (p[2 * i + 1] != 0) { is64 = 0; break; }
        g_is64 = is64;
    }
}

__global__ void k_zero(void) {
    int i = blockIdx.x * blockDim.x + threadIdx.x;
    if (i < NN) g_deg[i] = 0;
    if (i < HC) { g_chs1[i] = 0.0f; g_chs2[i] = 0.0f; }
}

// fp32 GEMM: 64 nodes per block, 128 threads (thread = output column).
// W read in native [k][c] layout -> warp-coalesced loads.
__global__ __launch_bounds__(128) void k_gemm(const float* __restrict__ x,
                                              const float* __restrict__ Wl,
                                              const float* __restrict__ Wr) {
    __shared__ float4 xs[64][32];           // 32 KB
    const int node0 = blockIdx.x * 64;
    const int c = threadIdx.x;

    const float4* x4 = (const float4*)x;
    #pragma unroll
    for (int i = 0; i < 16; i++) {
        int lin = threadIdx.x + i * 128;
        int row = lin >> 5, k4 = lin & 31;
        int node = node0 + row;
        xs[row][k4] = (node < NN) ? x4[(size_t)node * 32 + k4]
                                  : make_float4(0.f, 0.f, 0.f, 0.f);
    }
    __syncthreads();

    float acc[64];
    #pragma unroll
    for (int r = 0; r < 64; r++) acc[r] = 0.0f;
    #pragma unroll 2
    for (int k4 = 0; k4 < 32; k4++) {
        float w0 = Wl[(k4 * 4 + 0) * HC + c];
        float w1 = Wl[(k4 * 4 + 1) * HC + c];
        float w2 = Wl[(k4 * 4 + 2) * HC + c];
        float w3 = Wl[(k4 * 4 + 3) * HC + c];
        #pragma unroll
        for (int r = 0; r < 64; r++) {
            float4 xv = xs[r][k4];
            acc[r] += xv.x * w0 + xv.y * w1 + xv.z * w2 + xv.w * w3;
        }
    }
    #pragma unroll
    for (int r = 0; r < 64; r++) {
        int node = node0 + r;
        if (node < NN) g_xl[(size_t)node * HC + c] = acc[r];
    }

    #pragma unroll
    for (int r = 0; r < 64; r++) acc[r] = 0.0f;
    #pragma unroll 2
    for (int k4 = 0; k4 < 32; k4++) {
        float w0 = Wr[(k4 * 4 + 0) * HC + c];
        float w1 = Wr[(k4 * 4 + 1) * HC + c];
        float w2 = Wr[(k4 * 4 + 2) * HC + c];
        float w3 = Wr[(k4 * 4 + 3) * HC + c];
        #pragma unroll
        for (int r = 0; r < 64; r++) {
            float4 xv = xs[r][k4];
            acc[r] += xv.x * w0 + xv.y * w1 + xv.z * w2 + xv.w * w3;
        }
    }
    #pragma unroll
    for (int r = 0; r < 64; r++) {
        int node = node0 + r;
        if (node < NN) g_xr[(size_t)node * HC + c] = acc[r];
    }
}

// CSR build step 1: degree histogram
__global__ __launch_bounds__(256) void k_hist(const void* __restrict__ ei) {
    int e = blockIdx.x * blockDim.x + threadIdx.x;
    if (e >= ETOT) return;
    int src, dst;
    load_edge(ei, e, src, dst);
    (void)src;
    atomicAdd(&g_deg[dst], 1);
}

// CSR build step 2: single-block exclusive scan over degrees
__global__ __launch_bounds__(1024) void k_scan(void) {
    __shared__ int ssum[1024];
    const int C = (NN + 1023) / 1024;  // 49
    int t = threadIdx.x;
    int lo = t * C, hi = min(lo + C, NN);
    int s = 0;
    for (int i = lo; i < hi; i++) s += g_deg[i];
    ssum[t] = s;
    __syncthreads();
    for (int off = 1; off < 1024; off <<= 1) {
        int v = (t >= off) ? ssum[t - off] : 0;
        __syncthreads();
        ssum[t] += v;
        __syncthreads();
    }
    int excl = (t == 0) ? 0 : ssum[t - 1];
    for (int i = lo; i < hi; i++) {
        g_off[i] = excl;
        g_cursor[i] = excl;
        excl += g_deg[i];
    }
    if (t == 1023) g_off[NN] = ssum[1023];
}

// CSR build step 3: scatter srcs grouped by dst
__global__ __launch_bounds__(256) void k_scatter(const void* __restrict__ ei) {
    int e = blockIdx.x * blockDim.x + threadIdx.x;
    if (e >= ETOT) return;
    int src, dst;
    load_edge(ei, e, src, dst);
    int pos = atomicAdd(&g_cursor[dst], 1);
    g_esrc[pos] = src;
}

// FUSED edge pass: warp per node. Online softmax + aggregation, single gather,
// no atomics, no per-edge intermediate storage. Output includes bias.
__global__ __launch_bounds__(256) void k_edge(const float* __restrict__ att,
                                              const float* __restrict__ bias,
                                              float* __restrict__ out) {
    int n = (blockIdx.x * blockDim.x + threadIdx.x) >> 5;
    int lane = threadIdx.x & 31;
    if (n >= NN) return;
    int base = g_off[n];
    int deg = g_off[n + 1] - base;   // >= 1 (self-loop)

    float4 b = *(const float4*)(g_xr + (size_t)n * HC + lane * 4);
    float4 w = *(const float4*)(att + lane * 4);

    float m = -CUDART_INF_F, s = 0.0f;
    float4 acc = make_float4(0.f, 0.f, 0.f, 0.f);

    int src = g_esrc[base];
    float4 a = *(const float4*)(g_xl + (size_t)src * HC + lane * 4);
    for (int i = 0; i < deg; i++) {
        // prefetch next edge's features while computing this one
        int nsrc = (i + 1 < deg) ? g_esrc[base + i + 1] : 0;
        float4 an = *(const float4*)(g_xl + (size_t)nsrc * HC + lane * 4);

        float sx = a.x + b.x, sy = a.y + b.y, sz = a.z + b.z, sw = a.w + b.w;
        sx = (sx > 0.f) ? sx : NEG * sx;
        sy = (sy > 0.f) ? sy : NEG * sy;
        sz = (sz > 0.f) ? sz : NEG * sz;
        sw = (sw > 0.f) ? sw : NEG * sw;
        float p = sx * w.x + sy * w.y + sz * w.z + sw * w.w;
        p += __shfl_xor_sync(0xffffffffu, p, 1);
        p += __shfl_xor_sync(0xffffffffu, p, 2);
        p += __shfl_xor_sync(0xffffffffu, p, 4);
        p += __shfl_xor_sync(0xffffffffu, p, 8);
        // every lane now holds its own head's logit (head = lane>>4)

        float mn = fmaxf(m, p);
        float r  = __expf(m - mn);   // rescale old state (0 on first iter)
        float ep = __expf(p - mn);
        s = s * r + ep;
        acc.x = acc.x * r + ep * a.x;
        acc.y = acc.y * r + ep * a.y;
        acc.z = acc.z * r + ep * a.z;
        acc.w = acc.w * r + ep * a.w;
        m = mn;
        a = an;
    }
    float si = 1.0f / s;
    float4 bi = *(const float4*)(bias + lane * 4);
    float4 o = make_float4(acc.x * si + bi.x, acc.y * si + bi.y,
                           acc.z * si + bi.z, acc.w * si + bi.w);
    *(float4*)(out + (size_t)n * HC + lane * 4) = o;
}

// stats: thread = channel; block strides over node rows (out already has bias)
__global__ __launch_bounds__(128) void k_stats(const float* __restrict__ out) {
    int c = threadIdx.x;
    float s1 = 0.f, s2 = 0.f;
    for (int i = blockIdx.x; i < NN; i += gridDim.x) {
        float v = out[(size_t)i * HC + c];
        s1 += v;
        s2 += v * v;
    }
    atomicAdd(&g_chs1[c], s1);
    atomicAdd(&g_chs2[c], s2);
}

// norm: float4-vectorized, in place
__global__ void k_norm(float* __restrict__ out,
                       const float* __restrict__ gw,
                       const float* __restrict__ gb,
                       const float* __restrict__ gms) {
    const float invn = 1.0f / (float)NN;
    int stride = gridDim.x * blockDim.x;
    float4* o4 = (float4*)out;
    for (size_t i = blockIdx.x * blockDim.x + threadIdx.x; i < (size_t)NN * 32; i += stride) {
        int c4 = (int)(i & 31);
        float4 v = o4[i];
        #pragma unroll
        for (int j = 0; j < 4; j++) {
            int c = c4 * 4 + j;
            float mean = g_chs1[c] * invn;
            float m2   = g_chs2[c] * invn;
            float ms   = mean * __ldg(gms + c);
            float var  = m2 - 2.0f * ms * mean + ms * ms;
            float* pv = (&v.x) + j;
            *pv = __ldg(gw + c) * (*pv - ms) * rsqrtf(var + EPSV) + __ldg(gb + c);
        }
        o4[i] = v;
    }
}

// ---------------- launch ------------------------------------------------------
extern "C" void kernel_launch(void* const* d_in, const int* in_sizes, int n_in,
                              void* d_out, int out_size) {
    const float* x    = (const float*)d_in[0];
    const void*  ei   = d_in[1];
    const float* Wl   = (const float*)d_in[2];
    const float* Wr   = (const float*)d_in[3];
    const float* att  = (const float*)d_in[4];
    const float* bias = (const float*)d_in[5];
    const float* gw   = (const float*)d_in[6];
    const float* gb   = (const float*)d_in[7];
    const float* gms  = (const float*)d_in[8];
    float* out = (float*)d_out;

    k_detect<<<1, 32>>>(ei);
    k_zero<<<(NN + 255) / 256, 256>>>();
    k_gemm<<<(NN + 63) / 64, 128>>>(x, Wl, Wr);

    int eblk = (ETOT + 255) / 256;
    k_hist<<<eblk, 256>>>(ei);
    k_scan<<<1, 1024>>>();
    k_scatter<<<eblk, 256>>>(ei);

    int nblk = (NN * 32 + 255) / 256;  // warp per node
    k_edge<<<nblk, 256>>>(att, bias, out);

    k_stats<<<512, 128>>>(out);
    k_norm<<<4096, 256>>>(out, gw, gb, gms);
}

// round 8
// speedup vs baseline: 1.8215x; 1.1854x over previous
#include <cuda_runtime.h>
#include <cstdint>
#include <math_constants.h>

#define NN   50000
#define EE   1600000
#define ETOT (EE + NN)
#define HC   128
#define NH   2
#define NEG  0.2f
#define EPSV 1e-5f

// ---------------- scratch (device globals; no runtime allocation) ----------
__device__ float    g_xl[(size_t)NN * HC];      // x @ W_l   (25.6 MB)
__device__ float    g_xr[(size_t)NN * HC];      // x @ W_r   (25.6 MB)
__device__ int      g_esrc[ETOT];               // CSR src array (6.6 MB)
__device__ int      g_deg[NN];
__device__ int      g_off[NN + 1];
__device__ int      g_cursor[NN];
__device__ float    g_chs1[HC];
__device__ float    g_chs2[HC];
__device__ int      g_is64;

// ---------------- helpers ---------------------------------------------------
__device__ __forceinline__ void load_edge(const void* ei, int e, int& src, int& dst) {
    if (e >= EE) { src = dst = e - EE; return; }
    if (g_is64) {
        const long long* p = (const long long*)ei;
        src = (int)p[e]; dst = (int)p[EE + e];
    } else {
        const int* p = (const int*)ei;
        src = p[e]; dst = p[EE + e];
    }
}

__device__ __forceinline__ void tf32split(float v, uint32_t& hi, uint32_t& lo) {
    uint32_t h;
    asm("cvt.rna.tf32.f32 %0, %1;" : "=r"(h) : "f"(v));
    float l = v - __uint_as_float(h);
    uint32_t lr;
    asm("cvt.rna.tf32.f32 %0, %1;" : "=r"(lr) : "f"(l));
    hi = h; lo = lr;
}

__device__ __forceinline__ void mma8(float c[4], uint32_t a0, uint32_t a1,
                                     uint32_t a2, uint32_t a3,
                                     uint32_t b0, uint32_t b1) {
    asm volatile(
        "mma.sync.aligned.m16n8k8.row.col.f32.tf32.tf32.f32 "
        "{%0,%1,%2,%3}, {%4,%5,%6,%7}, {%8,%9}, {%0,%1,%2,%3};"
        : "+f"(c[0]), "+f"(c[1]), "+f"(c[2]), "+f"(c[3])
        : "r"(a0), "r"(a1), "r"(a2), "r"(a3), "r"(b0), "r"(b1));
}

// ---------------- kernels ----------------------------------------------------

__global__ void k_detect(const void* ei) {
    if (threadIdx.x == 0) {
        const int* p = (const int*)ei;
        int is64 = 1;
        #pragma unroll 1
        for (int i = 0; i < 64; i++)
            if (p[2 * i + 1] != 0) { is64 = 0; break; }
        g_is64 = is64;
    }
}

__global__ void k_zero(void) {
    int i = blockIdx.x * blockDim.x + threadIdx.x;
    if (i < NN) g_deg[i] = 0;
    if (i < HC) { g_chs1[i] = 0.0f; g_chs2[i] = 0.0f; }
}

// Tensor-core GEMM (3xTF32 split): 64 rows x 128 cols per block, 4 warps.
// x tile loaded once, used for both W_l and W_r products.
__global__ __launch_bounds__(128) void k_gemm(const float* __restrict__ x,
                                              const float* __restrict__ Wl,
                                              const float* __restrict__ Wr) {
    __shared__ float xs[64][132];   // 33792 B, padded: A-frag reads conflict-free
    __shared__ float ws[16][132];   //  8448 B, K-chunk of 16
    const int node0 = blockIdx.x * 64;
    const int t = threadIdx.x;
    const int warp = t >> 5, lane = t & 31;
    const int gid = lane >> 2, tig = lane & 3;
    const int m0 = warp * 16;

    // fill x tile (64 x 128 floats = 2048 float4)
    const float4* x4 = (const float4*)x;
    #pragma unroll
    for (int i = 0; i < 16; i++) {
        int lin = t + i * 128;
        int row = lin >> 5, c4 = lin & 31;
        int node = node0 + row;
        float4 v = (node < NN) ? x4[(size_t)node * 32 + c4]
                               : make_float4(0.f, 0.f, 0.f, 0.f);
        *(float4*)&xs[row][c4 * 4] = v;
    }

    const float* Wmat[2] = { Wl, Wr };
    float* Omat[2] = { g_xl, g_xr };

    #pragma unroll 1
    for (int g = 0; g < 2; g++) {
        const float* W = Wmat[g];
        float c[16][4];
        #pragma unroll
        for (int nt = 0; nt < 16; nt++)
            c[nt][0] = c[nt][1] = c[nt][2] = c[nt][3] = 0.0f;

        #pragma unroll 1
        for (int kc = 0; kc < 128; kc += 16) {
            __syncthreads();
            // load W chunk [16][128] (coalesced, 512 float4)
            #pragma unroll
            for (int i = 0; i < 4; i++) {
                int lin = t + i * 128;
                int row = lin >> 5, c4 = lin & 31;
                *(float4*)&ws[row][c4 * 4] =
                    *(const float4*)&W[(size_t)(kc + row) * 128 + c4 * 4];
            }
            __syncthreads();

            #pragma unroll
            for (int ks = 0; ks < 2; ks++) {
                int kk = ks * 8;
                float a0 = xs[m0 + gid][kc + kk + tig];
                float a1 = xs[m0 + gid + 8][kc + kk + tig];
                float a2 = xs[m0 + gid][kc + kk + tig + 4];
                float a3 = xs[m0 + gid + 8][kc + kk + tig + 4];
                uint32_t ah0, al0, ah1, al1, ah2, al2, ah3, al3;
                tf32split(a0, ah0, al0);
                tf32split(a1, ah1, al1);
                tf32split(a2, ah2, al2);
                tf32split(a3, ah3, al3);
                #pragma unroll
                for (int nt = 0; nt < 16; nt++) {
                    int n0 = nt * 8;
                    float b0 = ws[kk + tig][n0 + gid];
                    float b1 = ws[kk + tig + 4][n0 + gid];
                    uint32_t bh0, bl0, bh1, bl1;
                    tf32split(b0, bh0, bl0);
                    tf32split(b1, bh1, bl1);
                    mma8(c[nt], ah0, ah1, ah2, ah3, bh0, bh1);
                    mma8(c[nt], ah0, ah1, ah2, ah3, bl0, bl1);
                    mma8(c[nt], al0, al1, al2, al3, bh0, bh1);
                }
            }
        }
        // store: c0/c1 = (row gid, cols 2tig,2tig+1), c2/c3 = row gid+8
        float* O = Omat[g];
        int r0 = node0 + m0 + gid;
        int r1 = r0 + 8;
        #pragma unroll
        for (int nt = 0; nt < 16; nt++) {
            int col = nt * 8 + tig * 2;
            if (r0 < NN) *(float2*)&O[(size_t)r0 * HC + col] = make_float2(c[nt][0], c[nt][1]);
            if (r1 < NN) *(float2*)&O[(size_t)r1 * HC + col] = make_float2(c[nt][2], c[nt][3]);
        }
        __syncthreads();
    }
}

// CSR build step 1: degree histogram
__global__ __launch_bounds__(256) void k_hist(const void* __restrict__ ei) {
    int e = blockIdx.x * blockDim.x + threadIdx.x;
    if (e >= ETOT) return;
    int src, dst;
    load_edge(ei, e, src, dst);
    (void)src;
    atomicAdd(&g_deg[dst], 1);
}

// CSR build step 2: single-block exclusive scan over degrees
__global__ __launch_bounds__(1024) void k_scan(void) {
    __shared__ int ssum[1024];
    const int C = (NN + 1023) / 1024;
    int t = threadIdx.x;
    int lo = t * C, hi = min(lo + C, NN);
    int s = 0;
    for (int i = lo; i < hi; i++) s += g_deg[i];
    ssum[t] = s;
    __syncthreads();
    for (int off = 1; off < 1024; off <<= 1) {
        int v = (t >= off) ? ssum[t - off] : 0;
        __syncthreads();
        ssum[t] += v;
        __syncthreads();
    }
    int excl = (t == 0) ? 0 : ssum[t - 1];
    for (int i = lo; i < hi; i++) {
        g_off[i] = excl;
        g_cursor[i] = excl;
        excl += g_deg[i];
    }
    if (t == 1023) g_off[NN] = ssum[1023];
}

// CSR build step 3: scatter srcs grouped by dst
__global__ __launch_bounds__(256) void k_scatter(const void* __restrict__ ei) {
    int e = blockIdx.x * blockDim.x + threadIdx.x;
    if (e >= ETOT) return;
    int src, dst;
    load_edge(ei, e, src, dst);
    int pos = atomicAdd(&g_cursor[dst], 1);
    g_esrc[pos] = src;
}

// FUSED edge pass: warp per node. Online softmax + aggregation + GraphNorm
// stats. Single gather, no per-edge storage, 2-deep gather prefetch.
__global__ __launch_bounds__(256) void k_edge(const float* __restrict__ att,
                                              const float* __restrict__ bias,
                                              float* __restrict__ out) {
    __shared__ float ss1[HC], ss2[HC];
    int t = threadIdx.x;
    if (t < HC) { ss1[t] = 0.0f; ss2[t] = 0.0f; }
    __syncthreads();

    int n = (blockIdx.x * blockDim.x + t) >> 5;
    int lane = t & 31;
    bool valid = (n < NN);
    float4 o = make_float4(0.f, 0.f, 0.f, 0.f);

    if (valid) {
        int base = g_off[n];
        int deg = g_off[n + 1] - base;   // >= 1 (self-loop)
        const int* ep = g_esrc + base;

        float4 b = *(const float4*)(g_xr + (size_t)n * HC + lane * 4);
        float4 w = *(const float4*)(att + lane * 4);

        float m = -CUDART_INF_F, s = 0.0f;
        float4 acc = make_float4(0.f, 0.f, 0.f, 0.f);

        int s0 = ep[0];
        int s1 = (deg > 1) ? ep[1] : 0;
        float4 a0 = *(const float4*)(g_xl + (size_t)s0 * HC + lane * 4);
        float4 a1 = *(const float4*)(g_xl + (size_t)s1 * HC + lane * 4);

        for (int i = 0; i < deg; i++) {
            int s2 = (i + 2 < deg) ? ep[i + 2] : 0;
            float4 a2 = *(const float4*)(g_xl + (size_t)s2 * HC + lane * 4);

            float sx = a0.x + b.x, sy = a0.y + b.y, sz = a0.z + b.z, sw = a0.w + b.w;
            sx = (sx > 0.f) ? sx : NEG * sx;
            sy = (sy > 0.f) ? sy : NEG * sy;
            sz = (sz > 0.f) ? sz : NEG * sz;
            sw = (sw > 0.f) ? sw : NEG * sw;
            float p = sx * w.x + sy * w.y + sz * w.z + sw * w.w;
            p += __shfl_xor_sync(0xffffffffu, p, 1);
            p += __shfl_xor_sync(0xffffffffu, p, 2);
            p += __shfl_xor_sync(0xffffffffu, p, 4);
            p += __shfl_xor_sync(0xffffffffu, p, 8);
            // every lane holds its head's logit (head = lane>>4)

            float mn = fmaxf(m, p);
            float r  = __expf(m - mn);
            float ep2 = __expf(p - mn);
            s = s * r + ep2;
            acc.x = acc.x * r + ep2 * a0.x;
            acc.y = acc.y * r + ep2 * a0.y;
            acc.z = acc.z * r + ep2 * a0.z;
            acc.w = acc.w * r + ep2 * a0.w;
            m = mn;
            a0 = a1; a1 = a2;
        }
        float si = 1.0f / s;
        float4 bi = *(const float4*)(bias + lane * 4);
        o = make_float4(acc.x * si + bi.x, acc.y * si + bi.y,
                        acc.z * si + bi.z, acc.w * si + bi.w);
        *(float4*)(out + (size_t)n * HC + lane * 4) = o;

        // GraphNorm partial stats (block-local)
        int c = lane * 4;
        atomicAdd(&ss1[c + 0], o.x); atomicAdd(&ss2[c + 0], o.x * o.x);
        atomicAdd(&ss1[c + 1], o.y); atomicAdd(&ss2[c + 1], o.y * o.y);
        atomicAdd(&ss1[c + 2], o.z); atomicAdd(&ss2[c + 2], o.z * o.z);
        atomicAdd(&ss1[c + 3], o.w); atomicAdd(&ss2[c + 3], o.w * o.w);
    }
    __syncthreads();
    if (t < HC) {
        atomicAdd(&g_chs1[t], ss1[t]);
        atomicAdd(&g_chs2[t], ss2[t]);
    }
}

// norm: float4-vectorized, in place
__global__ void k_norm(float* __restrict__ out,
                       const float* __restrict__ gw,
                       const float* __restrict__ gb,
                       const float* __restrict__ gms) {
    const float invn = 1.0f / (float)NN;
    int stride = gridDim.x * blockDim.x;
    float4* o4 = (float4*)out;
    for (size_t i = blockIdx.x * blockDim.x + threadIdx.x; i < (size_t)NN * 32; i += stride) {
        int c4 = (int)(i & 31);
        float4 v = o4[i];
        #pragma unroll
        for (int j = 0; j < 4; j++) {
            int c = c4 * 4 + j;
            float mean = g_chs1[c] * invn;
            float m2   = g_chs2[c] * invn;
            float ms   = mean * __ldg(gms + c);
            float var  = m2 - 2.0f * ms * mean + ms * ms;
            float* pv = (&v.x) + j;
            *pv = __ldg(gw + c) * (*pv - ms) * rsqrtf(var + EPSV) + __ldg(gb + c);
        }
        o4[i] = v;
    }
}

// ---------------- launch ------------------------------------------------------
extern "C" void kernel_launch(void* const* d_in, const int* in_sizes, int n_in,
                              void* d_out, int out_size) {
    const float* x    = (const float*)d_in[0];
    const void*  ei   = d_in[1];
    const float* Wl   = (const float*)d_in[2];
    const float* Wr   = (const float*)d_in[3];
    const float* att  = (const float*)d_in[4];
    const float* bias = (const float*)d_in[5];
    const float* gw   = (const float*)d_in[6];
    const float* gb   = (const float*)d_in[7];
    const float* gms  = (const float*)d_in[8];
    float* out = (float*)d_out;

    k_detect<<<1, 32>>>(ei);
    k_zero<<<(NN + 255) / 256, 256>>>();
    k_gemm<<<(NN + 63) / 64, 128>>>(x, Wl, Wr);

    int eblk = (ETOT + 255) / 256;
    k_hist<<<eblk, 256>>>(ei);
    k_scan<<<1, 1024>>>();
    k_scatter<<<eblk, 256>>>(ei);

    int nblk = (NN * 32 + 255) / 256;  // warp per node
    k_edge<<<nblk, 256>>>(att, bias, out);

    k_norm<<<4096, 256>>>(out, gw, gb, gms);
}

// round 11
// speedup vs baseline: 1.8237x; 1.0012x over previous
#include <cuda_runtime.h>
#include <cuda_fp16.h>
#include <cstdint>
#include <math_constants.h>

#define NN   50000
#define EE   1600000
#define ETOT (EE + NN)
#define HC   128
#define NH   2
#define NEG  0.2f
#define EPSV 1e-5f

// ---------------- scratch (device globals; no runtime allocation) ----------
__device__ __half2  g_xlh[(size_t)NN * 64];     // x @ W_l in fp16 (12.8 MB)
__device__ float    g_xr[(size_t)NN * HC];      // x @ W_r   (25.6 MB)
__device__ int      g_esrc[ETOT];               // CSR src array (6.6 MB)
__device__ int      g_deg[NN];
__device__ int      g_off[NN + 1];
__device__ int      g_cursor[NN];
__device__ float    g_chs1[HC];
__device__ float    g_chs2[HC];
__device__ int      g_is64;

// ---------------- helpers ---------------------------------------------------
__device__ __forceinline__ void load_edge(const void* ei, int e, int& src, int& dst) {
    if (e >= EE) { src = dst = e - EE; return; }
    if (g_is64) {
        const long long* p = (const long long*)ei;
        src = (int)p[e]; dst = (int)p[EE + e];
    } else {
        const int* p = (const int*)ei;
        src = p[e]; dst = p[EE + e];
    }
}

__device__ __forceinline__ void tf32split(float v, uint32_t& hi, uint32_t& lo) {
    uint32_t h;
    asm("cvt.rna.tf32.f32 %0, %1;" : "=r"(h) : "f"(v));
    float l = v - __uint_as_float(h);
    uint32_t lr;
    asm("cvt.rna.tf32.f32 %0, %1;" : "=r"(lr) : "f"(l));
    hi = h; lo = lr;
}

__device__ __forceinline__ void mma8(float c[4], uint32_t a0, uint32_t a1,
                                     uint32_t a2, uint32_t a3,
                                     uint32_t b0, uint32_t b1) {
    asm volatile(
        "mma.sync.aligned.m16n8k8.row.col.f32.tf32.tf32.f32 "
        "{%0,%1,%2,%3}, {%4,%5,%6,%7}, {%8,%9}, {%0,%1,%2,%3};"
        : "+f"(c[0]), "+f"(c[1]), "+f"(c[2]), "+f"(c[3])
        : "r"(a0), "r"(a1), "r"(a2), "r"(a3), "r"(b0), "r"(b1));
}

// ---------------- kernels ----------------------------------------------------

__global__ void k_detect(const void* ei) {
    if (threadIdx.x == 0) {
        const int* p = (const int*)ei;
        int is64 = 1;
        #pragma unroll 1
        for (int i = 0; i < 64; i++)
            if (p[2 * i + 1] != 0) { is64 = 0; break; }
        g_is64 = is64;
    }
}

__global__ void k_zero(void) {
    int i = blockIdx.x * blockDim.x + threadIdx.x;
    if (i < NN) g_deg[i] = 0;
    if (i < HC) { g_chs1[i] = 0.0f; g_chs2[i] = 0.0f; }
}

// Tensor-core GEMM (3xTF32 split): 64 rows x 128 cols per block, 4 warps.
// x tile loaded once, used for both W_l (-> fp16) and W_r (-> fp32).
__global__ __launch_bounds__(128) void k_gemm(const float* __restrict__ x,
                                              const float* __restrict__ Wl,
                                              const float* __restrict__ Wr) {
    __shared__ float xs[64][132];
    __shared__ float ws[16][132];
    const int node0 = blockIdx.x * 64;
    const int t = threadIdx.x;
    const int warp = t >> 5, lane = t & 31;
    const int gid = lane >> 2, tig = lane & 3;
    const int m0 = warp * 16;

    const float4* x4 = (const float4*)x;
    #pragma unroll
    for (int i = 0; i < 16; i++) {
        int lin = t + i * 128;
        int row = lin >> 5, c4 = lin & 31;
        int node = node0 + row;
        float4 v = (node < NN) ? x4[(size_t)node * 32 + c4]
                               : make_float4(0.f, 0.f, 0.f, 0.f);
        *(float4*)&xs[row][c4 * 4] = v;
    }

    const float* Wmat[2] = { Wl, Wr };

    #pragma unroll 1
    for (int g = 0; g < 2; g++) {
        const float* W = Wmat[g];
        float c[16][4];
        #pragma unroll
        for (int nt = 0; nt < 16; nt++)
            c[nt][0] = c[nt][1] = c[nt][2] = c[nt][3] = 0.0f;

        #pragma unroll 1
        for (int kc = 0; kc < 128; kc += 16) {
            __syncthreads();
            #pragma unroll
            for (int i = 0; i < 4; i++) {
                int lin = t + i * 128;
                int row = lin >> 5, c4 = lin & 31;
                *(float4*)&ws[row][c4 * 4] =
                    *(const float4*)&W[(size_t)(kc + row) * 128 + c4 * 4];
            }
            __syncthreads();

            #pragma unroll
            for (int ks = 0; ks < 2; ks++) {
                int kk = ks * 8;
                float a0 = xs[m0 + gid][kc + kk + tig];
                float a1 = xs[m0 + gid + 8][kc + kk + tig];
                float a2 = xs[m0 + gid][kc + kk + tig + 4];
                float a3 = xs[m0 + gid + 8][kc + kk + tig + 4];
                uint32_t ah0, al0, ah1, al1, ah2, al2, ah3, al3;
                tf32split(a0, ah0, al0);
                tf32split(a1, ah1, al1);
                tf32split(a2, ah2, al2);
                tf32split(a3, ah3, al3);
                #pragma unroll
                for (int nt = 0; nt < 16; nt++) {
                    int n0 = nt * 8;
                    float b0 = ws[kk + tig][n0 + gid];
                    float b1 = ws[kk + tig + 4][n0 + gid];
                    uint32_t bh0, bl0, bh1, bl1;
                    tf32split(b0, bh0, bl0);
                    tf32split(b1, bh1, bl1);
                    mma8(c[nt], ah0, ah1, ah2, ah3, bh0, bh1);
                    mma8(c[nt], ah0, ah1, ah2, ah3, bl0, bl1);
                    mma8(c[nt], al0, al1, al2, al3, bh0, bh1);
                }
            }
        }
        int r0 = node0 + m0 + gid;
        int r1 = r0 + 8;
        if (g == 0) {
            // x_l -> fp16 (half2 per column pair)
            #pragma unroll
            for (int nt = 0; nt < 16; nt++) {
                int h2 = (nt * 8 + tig * 2) >> 1;   // half2 index (even col)
                if (r0 < NN) g_xlh[(size_t)r0 * 64 + h2] = __floats2half2_rn(c[nt][0], c[nt][1]);
                if (r1 < NN) g_xlh[(size_t)r1 * 64 + h2] = __floats2half2_rn(c[nt][2], c[nt][3]);
            }
        } else {
            #pragma unroll
            for (int nt = 0; nt < 16; nt++) {
                int col = nt * 8 + tig * 2;
                if (r0 < NN) *(float2*)&g_xr[(size_t)r0 * HC + col] = make_float2(c[nt][0], c[nt][1]);
                if (r1 < NN) *(float2*)&g_xr[(size_t)r1 * HC + col] = make_float2(c[nt][2], c[nt][3]);
            }
        }
        __syncthreads();
    }
}

// CSR build step 1: degree histogram (4 edges/thread for MLP)
__global__ __launch_bounds__(256) void k_hist(const void* __restrict__ ei) {
    int base = blockIdx.x * 1024 + threadIdx.x;
    #pragma unroll
    for (int j = 0; j < 4; j++) {
        int e = base + j * 256;
        if (e < ETOT) {
            int src, dst;
            load_edge(ei, e, src, dst);
            (void)src;
            atomicAdd(&g_deg[dst], 1);
        }
    }
}

// CSR build step 2: single-block exclusive scan over degrees
__global__ __launch_bounds__(1024) void k_scan(void) {
    __shared__ int ssum[1024];
    const int C = (NN + 1023) / 1024;
    int t = threadIdx.x;
    int lo = t * C, hi = min(lo + C, NN);
    int s = 0;
    for (int i = lo; i < hi; i++) s += g_deg[i];
    ssum[t] = s;
    __syncthreads();
    for (int off = 1; off < 1024; off <<= 1) {
        int v = (t >= off) ? ssum[t - off] : 0;
        __syncthreads();
        ssum[t] += v;
        __syncthreads();
    }
    int excl = (t == 0) ? 0 : ssum[t - 1];
    for (int i = lo; i < hi; i++) {
        g_off[i] = excl;
        g_cursor[i] = excl;
        excl += g_deg[i];
    }
    if (t == 1023) g_off[NN] = ssum[1023];
}

// CSR build step 3: scatter srcs grouped by dst (4 edges/thread)
__global__ __launch_bounds__(256) void k_scatter(const void* __restrict__ ei) {
    int base = blockIdx.x * 1024 + threadIdx.x;
    #pragma unroll
    for (int j = 0; j < 4; j++) {
        int e = base + j * 256;
        if (e < ETOT) {
            int src, dst;
            load_edge(ei, e, src, dst);
            int pos = atomicAdd(&g_cursor[dst], 1);
            g_esrc[pos] = src;
        }
    }
}

// FUSED edge pass: warp per node. fp16 gather of x_l, online softmax +
// aggregation + GraphNorm stats, 2-deep prefetch, no atomics on edges.
__global__ __launch_bounds__(256) void k_edge(const float* __restrict__ att,
                                              const float* __restrict__ bias,
                                              float* __restrict__ out) {
    __shared__ float ss1[HC], ss2[HC];
    int t = threadIdx.x;
    if (t < HC) { ss1[t] = 0.0f; ss2[t] = 0.0f; }
    __syncthreads();

    int n = (blockIdx.x * blockDim.x + t) >> 5;
    int lane = t & 31;

    if (n < NN) {
        int base = g_off[n];
        int deg = g_off[n + 1] - base;   // >= 1 (self-loop)
        const int* ep = g_esrc + base;

        float4 b = *(const float4*)(g_xr + (size_t)n * HC + lane * 4);
        float4 w = *(const float4*)(att + lane * 4);

        float m = -CUDART_INF_F, s = 0.0f;
        float4 acc = make_float4(0.f, 0.f, 0.f, 0.f);

        const __half2* XL = g_xlh;
        int s0 = ep[0];
        int s1 = (deg > 1) ? ep[1] : 0;
        uint2 r0 = *(const uint2*)(XL + (size_t)s0 * 64 + lane * 2);
        uint2 r1 = *(const uint2*)(XL + (size_t)s1 * 64 + lane * 2);

        for (int i = 0; i < deg; i++) {
            int s2 = (i + 2 < deg) ? ep[i + 2] : 0;
            uint2 r2 = *(const uint2*)(XL + (size_t)s2 * 64 + lane * 2);

            float2 alo = __half22float2(*(__half2*)&r0.x);
            float2 ahi = __half22float2(*(__half2*)&r0.y);

            float sx = alo.x + b.x, sy = alo.y + b.y, sz = ahi.x + b.z, sw = ahi.y + b.w;
            sx = (sx > 0.f) ? sx : NEG * sx;
            sy = (sy > 0.f) ? sy : NEG * sy;
            sz = (sz > 0.f) ? sz : NEG * sz;
            sw = (sw > 0.f) ? sw : NEG * sw;
            float p = sx * w.x + sy * w.y + sz * w.z + sw * w.w;
            p += __shfl_xor_sync(0xffffffffu, p, 1);
            p += __shfl_xor_sync(0xffffffffu, p, 2);
            p += __shfl_xor_sync(0xffffffffu, p, 4);
            p += __shfl_xor_sync(0xffffffffu, p, 8);
            // every lane holds its head's logit (head = lane>>4)

            float mn = fmaxf(m, p);
            float r  = __expf(m - mn);
            float e2 = __expf(p - mn);
            s = s * r + e2;
            acc.x = acc.x * r + e2 * alo.x;
            acc.y = acc.y * r + e2 * alo.y;
            acc.z = acc.z * r + e2 * ahi.x;
            acc.w = acc.w * r + e2 * ahi.y;
            m = mn;
            r0 = r1; r1 = r2;
        }
        float si = 1.0f / s;
        float4 bi = *(const float4*)(bias + lane * 4);
        float4 o = make_float4(acc.x * si + bi.x, acc.y * si + bi.y,
                               acc.z * si + bi.z, acc.w * si + bi.w);
        *(float4*)(out + (size_t)n * HC + lane * 4) = o;

        int c = lane * 4;
        atomicAdd(&ss1[c + 0], o.x); atomicAdd(&ss2[c + 0], o.x * o.x);
        atomicAdd(&ss1[c + 1], o.y); atomicAdd(&ss2[c + 1], o.y * o.y);
        atomicAdd(&ss1[c + 2], o.z); atomicAdd(&ss2[c + 2], o.z * o.z);
        atomicAdd(&ss1[c + 3], o.w); atomicAdd(&ss2[c + 3], o.w * o.w);
    }
    __syncthreads();
    if (t < HC) {
        atomicAdd(&g_chs1[t], ss1[t]);
        atomicAdd(&g_chs2[t], ss2[t]);
    }
}

// norm: float4-vectorized, in place
__global__ void k_norm(float* __restrict__ out,
                       const float* __restrict__ gw,
                       const float* __restrict__ gb,
                       const float* __restrict__ gms) {
    const float invn = 1.0f / (float)NN;
    int stride = gridDim.x * blockDim.x;
    float4* o4 = (float4*)out;
    for (size_t i = blockIdx.x * blockDim.x + threadIdx.x; i < (size_t)NN * 32; i += stride) {
        int c4 = (int)(i & 31);
        float4 v = o4[i];
        #pragma unroll
        for (int j = 0; j < 4; j++) {
            int c = c4 * 4 + j;
            float mean = g_chs1[c] * invn;
            float m2   = g_chs2[c] * invn;
            float ms   = mean * __ldg(gms + c);
            float var  = m2 - 2.0f * ms * mean + ms * ms;
            float* pv = (&v.x) + j;
            *pv = __ldg(gw + c) * (*pv - ms) * rsqrtf(var + EPSV) + __ldg(gb + c);
        }
        o4[i] = v;
    }
}

// ---------------- launch ------------------------------------------------------
extern "C" void kernel_launch(void* const* d_in, const int* in_sizes, int n_in,
                              void* d_out, int out_size) {
    const float* x    = (const float*)d_in[0];
    const void*  ei   = d_in[1];
    const float* Wl   = (const float*)d_in[2];
    const float* Wr   = (const float*)d_in[3];
    const float* att  = (const float*)d_in[4];
    const float* bias = (const float*)d_in[5];
    const float* gw   = (const float*)d_in[6];
    const float* gb   = (const float*)d_in[7];
    const float* gms  = (const float*)d_in[8];
    float* out = (float*)d_out;

    k_detect<<<1, 32>>>(ei);
    k_zero<<<(NN + 255) / 256, 256>>>();
    k_gemm<<<(NN + 63) / 64, 128>>>(x, Wl, Wr);

    int eblk4 = (ETOT + 1023) / 1024;
    k_hist<<<eblk4, 256>>>(ei);
    k_scan<<<1, 1024>>>();
    k_scatter<<<eblk4, 256>>>(ei);

    int nblk = (NN * 32 + 255) / 256;  // warp per node
    k_edge<<<nblk, 256>>>(att, bias, out);

    k_norm<<<4096, 256>>>(out, gw, gb, gms);
}

// round 12
// speedup vs baseline: 1.8644x; 1.0223x over previous
#include <cuda_runtime.h>
#include <cuda_fp16.h>
#include <cstdint>
#include <math_constants.h>

#define NN   50000
#define EE   1600000
#define ETOT (EE + NN)
#define HC   128
#define NH   2
#define NEG  0.2f
#define EPSV 1e-5f

#define GEMM_BLOCKS ((NN + 63) / 64)   // 782

// ---------------- scratch (device globals; no runtime allocation) ----------
__device__ __half2  g_xlh[(size_t)NN * 64];     // x @ W_l in fp16 (12.8 MB)
__device__ float    g_xr[(size_t)NN * HC];      // x @ W_r   (25.6 MB)
__device__ int      g_esrc[ETOT];               // CSR src array (6.6 MB)
__device__ int      g_deg[NN];
__device__ int      g_off[NN + 1];
__device__ int      g_cursor[NN];
__device__ float    g_chs1[HC];
__device__ float    g_chs2[HC];
__device__ int      g_is64;

// ---------------- helpers ---------------------------------------------------
__device__ __forceinline__ void load_edge(const void* ei, int e, int& src, int& dst) {
    if (e >= EE) { src = dst = e - EE; return; }
    if (g_is64) {
        const long long* p = (const long long*)ei;
        src = (int)p[e]; dst = (int)p[EE + e];
    } else {
        const int* p = (const int*)ei;
        src = p[e]; dst = p[EE + e];
    }
}

__device__ __forceinline__ void tf32split(float v, uint32_t& hi, uint32_t& lo) {
    uint32_t h;
    asm("cvt.rna.tf32.f32 %0, %1;" : "=r"(h) : "f"(v));
    float l = v - __uint_as_float(h);
    uint32_t lr;
    asm("cvt.rna.tf32.f32 %0, %1;" : "=r"(lr) : "f"(l));
    hi = h; lo = lr;
}

__device__ __forceinline__ void mma8(float c[4], uint32_t a0, uint32_t a1,
                                     uint32_t a2, uint32_t a3,
                                     uint32_t b0, uint32_t b1) {
    asm volatile(
        "mma.sync.aligned.m16n8k8.row.col.f32.tf32.tf32.f32 "
        "{%0,%1,%2,%3}, {%4,%5,%6,%7}, {%8,%9}, {%0,%1,%2,%3};"
        : "+f"(c[0]), "+f"(c[1]), "+f"(c[2]), "+f"(c[3])
        : "r"(a0), "r"(a1), "r"(a2), "r"(a3), "r"(b0), "r"(b1));
}

// ---------------- kernels ----------------------------------------------------

__global__ void k_detect(const void* ei) {
    if (threadIdx.x == 0) {
        const int* p = (const int*)ei;
        int is64 = 1;
        #pragma unroll 1
        for (int i = 0; i < 64; i++)
            if (p[2 * i + 1] != 0) { is64 = 0; break; }
        g_is64 = is64;
    }
}

__global__ void k_zero(void) {
    int i = blockIdx.x * blockDim.x + threadIdx.x;
    if (i < NN) g_deg[i] = 0;
    if (i < HC) { g_chs1[i] = 0.0f; g_chs2[i] = 0.0f; }
}

// Tensor-core GEMM (3xTF32 split) with fused degree histogram tail.
// 64 rows x 128 cols per block, 4 warps; each block then processes its
// slice of edges for the histogram (overlaps latency-bound atomics with
// tensor-bound work across blocks).
__global__ __launch_bounds__(128) void k_gemm(const float* __restrict__ x,
                                              const float* __restrict__ Wl,
                                              const float* __restrict__ Wr,
                                              const void* __restrict__ ei) {
    __shared__ float xs[64][132];
    __shared__ float ws[16][132];
    const int node0 = blockIdx.x * 64;
    const int t = threadIdx.x;
    const int warp = t >> 5, lane = t & 31;
    const int gid = lane >> 2, tig = lane & 3;
    const int m0 = warp * 16;

    const float4* x4 = (const float4*)x;
    #pragma unroll
    for (int i = 0; i < 16; i++) {
        int lin = t + i * 128;
        int row = lin >> 5, c4 = lin & 31;
        int node = node0 + row;
        float4 v = (node < NN) ? x4[(size_t)node * 32 + c4]
                               : make_float4(0.f, 0.f, 0.f, 0.f);
        *(float4*)&xs[row][c4 * 4] = v;
    }

    const float* Wmat[2] = { Wl, Wr };

    #pragma unroll 1
    for (int g = 0; g < 2; g++) {
        const float* W = Wmat[g];
        float c[16][4];
        #pragma unroll
        for (int nt = 0; nt < 16; nt++)
            c[nt][0] = c[nt][1] = c[nt][2] = c[nt][3] = 0.0f;

        #pragma unroll 1
        for (int kc = 0; kc < 128; kc += 16) {
            __syncthreads();
            #pragma unroll
            for (int i = 0; i < 4; i++) {
                int lin = t + i * 128;
                int row = lin >> 5, c4 = lin & 31;
                *(float4*)&ws[row][c4 * 4] =
                    *(const float4*)&W[(size_t)(kc + row) * 128 + c4 * 4];
            }
            __syncthreads();

            #pragma unroll
            for (int ks = 0; ks < 2; ks++) {
                int kk = ks * 8;
                float a0 = xs[m0 + gid][kc + kk + tig];
                float a1 = xs[m0 + gid + 8][kc + kk + tig];
                float a2 = xs[m0 + gid][kc + kk + tig + 4];
                float a3 = xs[m0 + gid + 8][kc + kk + tig + 4];
                uint32_t ah0, al0, ah1, al1, ah2, al2, ah3, al3;
                tf32split(a0, ah0, al0);
                tf32split(a1, ah1, al1);
                tf32split(a2, ah2, al2);
                tf32split(a3, ah3, al3);
                #pragma unroll
                for (int nt = 0; nt < 16; nt++) {
                    int n0 = nt * 8;
                    float b0 = ws[kk + tig][n0 + gid];
                    float b1 = ws[kk + tig + 4][n0 + gid];
                    uint32_t bh0, bl0, bh1, bl1;
                    tf32split(b0, bh0, bl0);
                    tf32split(b1, bh1, bl1);
                    mma8(c[nt], ah0, ah1, ah2, ah3, bh0, bh1);
                    mma8(c[nt], ah0, ah1, ah2, ah3, bl0, bl1);
                    mma8(c[nt], al0, al1, al2, al3, bh0, bh1);
                }
            }
        }
        int r0 = node0 + m0 + gid;
        int r1 = r0 + 8;
        if (g == 0) {
            #pragma unroll
            for (int nt = 0; nt < 16; nt++) {
                int h2 = (nt * 8 + tig * 2) >> 1;
                if (r0 < NN) g_xlh[(size_t)r0 * 64 + h2] = __floats2half2_rn(c[nt][0], c[nt][1]);
                if (r1 < NN) g_xlh[(size_t)r1 * 64 + h2] = __floats2half2_rn(c[nt][2], c[nt][3]);
            }
        } else {
            #pragma unroll
            for (int nt = 0; nt < 16; nt++) {
                int col = nt * 8 + tig * 2;
                if (r0 < NN) *(float2*)&g_xr[(size_t)r0 * HC + col] = make_float2(c[nt][0], c[nt][1]);
                if (r1 < NN) *(float2*)&g_xr[(size_t)r1 * HC + col] = make_float2(c[nt][2], c[nt][3]);
            }
        }
        __syncthreads();
    }

    // ---- fused degree histogram tail: this block's slice of edges ----
    const int EPB = (ETOT + GEMM_BLOCKS - 1) / GEMM_BLOCKS;   // edges per block
    int e0 = blockIdx.x * EPB;
    int e1 = min(e0 + EPB, ETOT);
    for (int e = e0 + t; e < e1; e += 128) {
        int src, dst;
        load_edge(ei, e, src, dst);
        (void)src;
        atomicAdd(&g_deg[dst], 1);
    }
}

// CSR build step 2: single-block exclusive scan over degrees
__global__ __launch_bounds__(1024) void k_scan(void) {
    __shared__ int ssum[1024];
    const int C = (NN + 1023) / 1024;
    int t = threadIdx.x;
    int lo = t * C, hi = min(lo + C, NN);
    int s = 0;
    for (int i = lo; i < hi; i++) s += g_deg[i];
    ssum[t] = s;
    __syncthreads();
    for (int off = 1; off < 1024; off <<= 1) {
        int v = (t >= off) ? ssum[t - off] : 0;
        __syncthreads();
        ssum[t] += v;
        __syncthreads();
    }
    int excl = (t == 0) ? 0 : ssum[t - 1];
    for (int i = lo; i < hi; i++) {
        g_off[i] = excl;
        g_cursor[i] = excl;
        excl += g_deg[i];
    }
    if (t == 1023) g_off[NN] = ssum[1023];
}

// CSR build step 3: scatter srcs grouped by dst (4 edges/thread)
__global__ __launch_bounds__(256) void k_scatter(const void* __restrict__ ei) {
    int base = blockIdx.x * 1024 + threadIdx.x;
    #pragma unroll
    for (int j = 0; j < 4; j++) {
        int e = base + j * 256;
        if (e < ETOT) {
            int src, dst;
            load_edge(ei, e, src, dst);
            int pos = atomicAdd(&g_cursor[dst], 1);
            g_esrc[pos] = src;
        }
    }
}

// FUSED edge pass: warp per node. Fixed-baseline softmax (first edge's logit)
// -> NO loop-carried dependency through max/rescale; shfl+MUFU latency
// pipelines across edges. fp16 gather, 2-deep prefetch, fused stats.
__global__ __launch_bounds__(256) void k_edge(const float* __restrict__ att,
                                              const float* __restrict__ bias,
                                              float* __restrict__ out) {
    __shared__ float ss1[HC], ss2[HC];
    int t = threadIdx.x;
    if (t < HC) { ss1[t] = 0.0f; ss2[t] = 0.0f; }
    __syncthreads();

    int n = (blockIdx.x * blockDim.x + t) >> 5;
    int lane = t & 31;

    if (n < NN) {
        int base = g_off[n];
        int deg = g_off[n + 1] - base;   // >= 1 (self-loop)
        const int* ep = g_esrc + base;

        float4 b = *(const float4*)(g_xr + (size_t)n * HC + lane * 4);
        float4 w = *(const float4*)(att + lane * 4);

        float s = 0.0f, p0 = 0.0f;
        float4 acc = make_float4(0.f, 0.f, 0.f, 0.f);

        const __half2* XL = g_xlh;
        int s0 = ep[0];
        int s1 = (deg > 1) ? ep[1] : s0;
        uint2 r0 = *(const uint2*)(XL + (size_t)s0 * 64 + lane * 2);
        uint2 r1 = *(const uint2*)(XL + (size_t)s1 * 64 + lane * 2);

        #pragma unroll 2
        for (int i = 0; i < deg; i++) {
            int s2 = (i + 2 < deg) ? ep[i + 2] : 0;
            uint2 r2 = *(const uint2*)(XL + (size_t)s2 * 64 + lane * 2);

            float2 alo = __half22float2(*(__half2*)&r0.x);
            float2 ahi = __half22float2(*(__half2*)&r0.y);

            float sx = alo.x + b.x, sy = alo.y + b.y, sz = ahi.x + b.z, sw = ahi.y + b.w;
            sx = (sx > 0.f) ? sx : NEG * sx;
            sy = (sy > 0.f) ? sy : NEG * sy;
            sz = (sz > 0.f) ? sz : NEG * sz;
            sw = (sw > 0.f) ? sw : NEG * sw;
            float p = sx * w.x + sy * w.y + sz * w.z + sw * w.w;
            p += __shfl_xor_sync(0xffffffffu, p, 1);
            p += __shfl_xor_sync(0xffffffffu, p, 2);
            p += __shfl_xor_sync(0xffffffffu, p, 4);
            p += __shfl_xor_sync(0xffffffffu, p, 8);
            // every lane holds its head's logit (head = lane>>4)

            if (i == 0) p0 = p;          // fixed baseline; exp(0)=1 for edge 0
            float e2 = __expf(p - p0);
            s += e2;
            acc.x += e2 * alo.x;
            acc.y += e2 * alo.y;
            acc.z += e2 * ahi.x;
            acc.w += e2 * ahi.y;
            r0 = r1; r1 = r2;
        }
        float si = 1.0f / s;
        float4 bi = *(const float4*)(bias + lane * 4);
        float4 o = make_float4(acc.x * si + bi.x, acc.y * si + bi.y,
                               acc.z * si + bi.z, acc.w * si + bi.w);
        *(float4*)(out + (size_t)n * HC + lane * 4) = o;

        int c = lane * 4;
        atomicAdd(&ss1[c + 0], o.x); atomicAdd(&ss2[c + 0], o.x * o.x);
        atomicAdd(&ss1[c + 1], o.y); atomicAdd(&ss2[c + 1], o.y * o.y);
        atomicAdd(&ss1[c + 2], o.z); atomicAdd(&ss2[c + 2], o.z * o.z);
        atomicAdd(&ss1[c + 3], o.w); atomicAdd(&ss2[c + 3], o.w * o.w);
    }
    __syncthreads();
    if (t < HC) {
        atomicAdd(&g_chs1[t], ss1[t]);
        atomicAdd(&g_chs2[t], ss2[t]);
    }
}

// norm: float4-vectorized, in place
__global__ void k_norm(float* __restrict__ out,
                       const float* __restrict__ gw,
                       const float* __restrict__ gb,
                       const float* __restrict__ gms) {
    const float invn = 1.0f / (float)NN;
    int stride = gridDim.x * blockDim.x;
    float4* o4 = (float4*)out;
    for (size_t i = blockIdx.x * blockDim.x + threadIdx.x; i < (size_t)NN * 32; i += stride) {
        int c4 = (int)(i & 31);
        float4 v = o4[i];
        #pragma unroll
        for (int j = 0; j < 4; j++) {
            int c = c4 * 4 + j;
            float mean = g_chs1[c] * invn;
            float m2   = g_chs2[c] * invn;
            float ms   = mean * __ldg(gms + c);
            float var  = m2 - 2.0f * ms * mean + ms * ms;
            float* pv = (&v.x) + j;
            *pv = __ldg(gw + c) * (*pv - ms) * rsqrtf(var + EPSV) + __ldg(gb + c);
        }
        o4[i] = v;
    }
}

// ---------------- launch ------------------------------------------------------
extern "C" void kernel_launch(void* const* d_in, const int* in_sizes, int n_in,
                              void* d_out, int out_size) {
    const float* x    = (const float*)d_in[0];
    const void*  ei   = d_in[1];
    const float* Wl   = (const float*)d_in[2];
    const float* Wr   = (const float*)d_in[3];
    const float* att  = (const float*)d_in[4];
    const float* bias = (const float*)d_in[5];
    const float* gw   = (const float*)d_in[6];
    const float* gb   = (const float*)d_in[7];
    const float* gms  = (const float*)d_in[8];
    float* out = (float*)d_out;

    k_detect<<<1, 32>>>(ei);
    k_zero<<<(NN + 255) / 256, 256>>>();
    k_gemm<<<GEMM_BLOCKS, 128>>>(x, Wl, Wr, ei);   // gemm + fused histogram

    k_scan<<<1, 1024>>>();
    int eblk4 = (ETOT + 1023) / 1024;
    k_scatter<<<eblk4, 256>>>(ei);

    int nblk = (NN * 32 + 255) / 256;  // warp per node
    k_edge<<<nblk, 256>>>(att, bias, out);

    k_norm<<<4096, 256>>>(out, gw, gb, gms);
}

// round 14
// speedup vs baseline: 2.3929x; 1.2835x over previous
#include <cuda_runtime.h>
#include <cuda_fp16.h>
#include <cstdint>
#include <math_constants.h>

#define NN   50000
#define EE   1600000
#define ETOT (EE + NN)
#define HC   128
#define NH   2
#define NEG  0.2f
#define EPSV 1e-5f

#define GEMM_BLOCKS ((NN + 63) / 64)    // 782
#define SCAN_BLOCKS ((NN + 255) / 256)  // 196

// ---------------- scratch (device globals; no runtime allocation) ----------
__device__ __half2  g_xlh[(size_t)NN * 64];     // x @ W_l in fp16 (12.8 MB)
__device__ float    g_xr[(size_t)NN * HC];      // x @ W_r   (25.6 MB)
__device__ int      g_esrc[ETOT];               // CSR src array (6.6 MB)
__device__ int      g_deg[NN];
__device__ int      g_off[NN + 1];
__device__ int      g_cursor[NN];
__device__ int      g_bsum[SCAN_BLOCKS];        // per-block degree totals
__device__ int      g_bsumx[SCAN_BLOCKS];       // exclusive-scanned block totals
__device__ float    g_chs1[HC];
__device__ float    g_chs2[HC];
__device__ int      g_is64;

// ---------------- helpers ---------------------------------------------------
__device__ __forceinline__ void load_edge(const void* ei, int e, int& src, int& dst) {
    if (e >= EE) { src = dst = e - EE; return; }
    if (g_is64) {
        const long long* p = (const long long*)ei;
        src = (int)p[e]; dst = (int)p[EE + e];
    } else {
        const int* p = (const int*)ei;
        src = p[e]; dst = p[EE + e];
    }
}

__device__ __forceinline__ void tf32split(float v, uint32_t& hi, uint32_t& lo) {
    uint32_t h;
    asm("cvt.rna.tf32.f32 %0, %1;" : "=r"(h) : "f"(v));
    float l = v - __uint_as_float(h);
    uint32_t lr;
    asm("cvt.rna.tf32.f32 %0, %1;" : "=r"(lr) : "f"(l));
    hi = h; lo = lr;
}

__device__ __forceinline__ void mma8(float c[4], uint32_t a0, uint32_t a1,
                                     uint32_t a2, uint32_t a3,
                                     uint32_t b0, uint32_t b1) {
    asm volatile(
        "mma.sync.aligned.m16n8k8.row.col.f32.tf32.tf32.f32 "
        "{%0,%1,%2,%3}, {%4,%5,%6,%7}, {%8,%9}, {%0,%1,%2,%3};"
        : "+f"(c[0]), "+f"(c[1]), "+f"(c[2]), "+f"(c[3])
        : "r"(a0), "r"(a1), "r"(a2), "r"(a3), "r"(b0), "r"(b1));
}

// block-local inclusive scan of one int per thread (256 threads)
__device__ __forceinline__ int block_scan_incl(int v, int t) {
    __shared__ int sw[8];                 // per-warp totals
    int lane = t & 31, warp = t >> 5;
    // warp inclusive scan
    #pragma unroll
    for (int off = 1; off < 32; off <<= 1) {
        int u = __shfl_up_sync(0xffffffffu, v, off);
        if (lane >= off) v += u;
    }
    if (lane == 31) sw[warp] = v;
    __syncthreads();
    if (warp == 0) {
        int wv = (lane < 8) ? sw[lane] : 0;
        #pragma unroll
        for (int off = 1; off < 8; off <<= 1) {
            int u = __shfl_up_sync(0xffffffffu, wv, off);
            if (lane >= off) wv += u;
        }
        if (lane < 8) sw[lane] = wv;
    }
    __syncthreads();
    if (warp > 0) v += sw[warp - 1];
    return v;
}

// ---------------- kernels ----------------------------------------------------

__global__ void k_detect(const void* ei) {
    if (threadIdx.x == 0) {
        const int* p = (const int*)ei;
        int is64 = 1;
        #pragma unroll 1
        for (int i = 0; i < 64; i++)
            if (p[2 * i + 1] != 0) { is64 = 0; break; }
        g_is64 = is64;
    }
}

__global__ void k_zero(void) {
    int i = blockIdx.x * blockDim.x + threadIdx.x;
    if (i < NN) g_deg[i] = 0;
    if (i < HC) { g_chs1[i] = 0.0f; g_chs2[i] = 0.0f; }
}

// Tensor-core GEMM (3xTF32 split) with fused degree histogram tail.
__global__ __launch_bounds__(128) void k_gemm(const float* __restrict__ x,
                                              const float* __restrict__ Wl,
                                              const float* __restrict__ Wr,
                                              const void* __restrict__ ei) {
    __shared__ float xs[64][132];
    __shared__ float ws[16][132];
    const int node0 = blockIdx.x * 64;
    const int t = threadIdx.x;
    const int warp = t >> 5, lane = t & 31;
    const int gid = lane >> 2, tig = lane & 3;
    const int m0 = warp * 16;

    const float4* x4 = (const float4*)x;
    #pragma unroll
    for (int i = 0; i < 16; i++) {
        int lin = t + i * 128;
        int row = lin >> 5, c4 = lin & 31;
        int node = node0 + row;
        float4 v = (node < NN) ? x4[(size_t)node * 32 + c4]
                               : make_float4(0.f, 0.f, 0.f, 0.f);
        *(float4*)&xs[row][c4 * 4] = v;
    }

    const float* Wmat[2] = { Wl, Wr };

    #pragma unroll 1
    for (int g = 0; g < 2; g++) {
        const float* W = Wmat[g];
        float c[16][4];
        #pragma unroll
        for (int nt = 0; nt < 16; nt++)
            c[nt][0] = c[nt][1] = c[nt][2] = c[nt][3] = 0.0f;

        #pragma unroll 1
        for (int kc = 0; kc < 128; kc += 16) {
            __syncthreads();
            #pragma unroll
            for (int i = 0; i < 4; i++) {
                int lin = t + i * 128;
                int row = lin >> 5, c4 = lin & 31;
                *(float4*)&ws[row][c4 * 4] =
                    *(const float4*)&W[(size_t)(kc + row) * 128 + c4 * 4];
            }
            __syncthreads();

            #pragma unroll
            for (int ks = 0; ks < 2; ks++) {
                int kk = ks * 8;
                float a0 = xs[m0 + gid][kc + kk + tig];
                float a1 = xs[m0 + gid + 8][kc + kk + tig];
                float a2 = xs[m0 + gid][kc + kk + tig + 4];
                float a3 = xs[m0 + gid + 8][kc + kk + tig + 4];
                uint32_t ah0, al0, ah1, al1, ah2, al2, ah3, al3;
                tf32split(a0, ah0, al0);
                tf32split(a1, ah1, al1);
                tf32split(a2, ah2, al2);
                tf32split(a3, ah3, al3);
                #pragma unroll
                for (int nt = 0; nt < 16; nt++) {
                    int n0 = nt * 8;
                    float b0 = ws[kk + tig][n0 + gid];
                    float b1 = ws[kk + tig + 4][n0 + gid];
                    uint32_t bh0, bl0, bh1, bl1;
                    tf32split(b0, bh0, bl0);
                    tf32split(b1, bh1, bl1);
                    mma8(c[nt], ah0, ah1, ah2, ah3, bh0, bh1);
                    mma8(c[nt], ah0, ah1, ah2, ah3, bl0, bl1);
                    mma8(c[nt], al0, al1, al2, al3, bh0, bh1);
                }
            }
        }
        int r0 = node0 + m0 + gid;
        int r1 = r0 + 8;
        if (g == 0) {
            #pragma unroll
            for (int nt = 0; nt < 16; nt++) {
                int h2 = (nt * 8 + tig * 2) >> 1;
                if (r0 < NN) g_xlh[(size_t)r0 * 64 + h2] = __floats2half2_rn(c[nt][0], c[nt][1]);
                if (r1 < NN) g_xlh[(size_t)r1 * 64 + h2] = __floats2half2_rn(c[nt][2], c[nt][3]);
            }
        } else {
            #pragma unroll
            for (int nt = 0; nt < 16; nt++) {
                int col = nt * 8 + tig * 2;
                if (r0 < NN) *(float2*)&g_xr[(size_t)r0 * HC + col] = make_float2(c[nt][0], c[nt][1]);
                if (r1 < NN) *(float2*)&g_xr[(size_t)r1 * HC + col] = make_float2(c[nt][2], c[nt][3]);
            }
        }
        __syncthreads();
    }

    // ---- fused degree histogram tail ----
    const int EPB = (ETOT + GEMM_BLOCKS - 1) / GEMM_BLOCKS;
    int e0 = blockIdx.x * EPB;
    int e1 = min(e0 + EPB, ETOT);
    for (int e = e0 + t; e < e1; e += 128) {
        int src, dst;
        load_edge(ei, e, src, dst);
        (void)src;
        atomicAdd(&g_deg[dst], 1);
    }
}

// scan phase 1: per-block totals of 256 degrees
__global__ __launch_bounds__(256) void k_scan1(void) {
    int i = blockIdx.x * 256 + threadIdx.x;
    int d = (i < NN) ? g_deg[i] : 0;
    int incl = block_scan_incl(d, threadIdx.x);
    if (threadIdx.x == 255) g_bsum[blockIdx.x] = incl;
    g_off[min(i, NN)] = incl - d;    // block-local exclusive (fixed up in phase 3)
}

// scan phase 2: exclusive scan of 196 block totals (single block)
__global__ __launch_bounds__(256) void k_scan2(void) {
    int t = threadIdx.x;
    int v = (t < SCAN_BLOCKS) ? g_bsum[t] : 0;
    int incl = block_scan_incl(v, t);
    if (t < SCAN_BLOCKS) g_bsumx[t] = incl - v;
    if (t == SCAN_BLOCKS - 1) g_off[NN] = incl;
}

// scan phase 3: add block offsets, init cursors
__global__ __launch_bounds__(256) void k_scan3(void) {
    int i = blockIdx.x * 256 + threadIdx.x;
    if (i < NN) {
        int o = g_off[i] + g_bsumx[blockIdx.x];
        g_off[i] = o;
        g_cursor[i] = o;
    }
}

// CSR scatter: srcs grouped by dst (4 edges/thread)
__global__ __launch_bounds__(256) void k_scatter(const void* __restrict__ ei) {
    int base = blockIdx.x * 1024 + threadIdx.x;
    #pragma unroll
    for (int j = 0; j < 4; j++) {
        int e = base + j * 256;
        if (e < ETOT) {
            int src, dst;
            load_edge(ei, e, src, dst);
            int pos = atomicAdd(&g_cursor[dst], 1);
            g_esrc[pos] = src;
        }
    }
}

// FUSED edge pass: warp per node, fixed-baseline softmax, fp16 gather,
// 2-deep prefetch, fused GraphNorm stats.
__global__ __launch_bounds__(256) void k_edge(const float* __restrict__ att,
                                              const float* __restrict__ bias,
                                              float* __restrict__ out) {
    __shared__ float ss1[HC], ss2[HC];
    int t = threadIdx.x;
    if (t < HC) { ss1[t] = 0.0f; ss2[t] = 0.0f; }
    __syncthreads();

    int n = (blockIdx.x * blockDim.x + t) >> 5;
    int lane = t & 31;

    if (n < NN) {
        int base = g_off[n];
        int deg = g_off[n + 1] - base;   // >= 1 (self-loop)
        const int* ep = g_esrc + base;

        float4 b = *(const float4*)(g_xr + (size_t)n * HC + lane * 4);
        float4 w = *(const float4*)(att + lane * 4);

        float s = 0.0f, p0 = 0.0f;
        float4 acc = make_float4(0.f, 0.f, 0.f, 0.f);

        const __half2* XL = g_xlh;
        int s0 = ep[0];
        int s1 = (deg > 1) ? ep[1] : s0;
        uint2 r0 = *(const uint2*)(XL + (size_t)s0 * 64 + lane * 2);
        uint2 r1 = *(const uint2*)(XL + (size_t)s1 * 64 + lane * 2);

        #pragma unroll 2
        for (int i = 0; i < deg; i++) {
            int s2 = (i + 2 < deg) ? ep[i + 2] : 0;
            uint2 r2 = *(const uint2*)(XL + (size_t)s2 * 64 + lane * 2);

            float2 alo = __half22float2(*(__half2*)&r0.x);
            float2 ahi = __half22float2(*(__half2*)&r0.y);

            float sx = alo.x + b.x, sy = alo.y + b.y, sz = ahi.x + b.z, sw = ahi.y + b.w;
            sx = (sx > 0.f) ? sx : NEG * sx;
            sy = (sy > 0.f) ? sy : NEG * sy;
            sz = (sz > 0.f) ? sz : NEG * sz;
            sw = (sw > 0.f) ? sw : NEG * sw;
            float p = sx * w.x + sy * w.y + sz * w.z + sw * w.w;
            p += __shfl_xor_sync(0xffffffffu, p, 1);
            p += __shfl_xor_sync(0xffffffffu, p, 2);
            p += __shfl_xor_sync(0xffffffffu, p, 4);
            p += __shfl_xor_sync(0xffffffffu, p, 8);

            if (i == 0) p0 = p;          // fixed baseline
            float e2 = __expf(p - p0);
            s += e2;
            acc.x += e2 * alo.x;
            acc.y += e2 * alo.y;
            acc.z += e2 * ahi.x;
            acc.w += e2 * ahi.y;
            r0 = r1; r1 = r2;
        }
        float si = 1.0f / s;
        float4 bi = *(const float4*)(bias + lane * 4);
        float4 o = make_float4(acc.x * si + bi.x, acc.y * si + bi.y,
                               acc.z * si + bi.z, acc.w * si + bi.w);
        *(float4*)(out + (size_t)n * HC + lane * 4) = o;

        int c = lane * 4;
        atomicAdd(&ss1[c + 0], o.x); atomicAdd(&ss2[c + 0], o.x * o.x);
        atomicAdd(&ss1[c + 1], o.y); atomicAdd(&ss2[c + 1], o.y * o.y);
        atomicAdd(&ss1[c + 2], o.z); atomicAdd(&ss2[c + 2], o.z * o.z);
        atomicAdd(&ss1[c + 3], o.w); atomicAdd(&ss2[c + 3], o.w * o.w);
    }
    __syncthreads();
    if (t < HC) {
        atomicAdd(&g_chs1[t], ss1[t]);
        atomicAdd(&g_chs2[t], ss2[t]);
    }
}

// norm: float4-vectorized, in place
__global__ void k_norm(float* __restrict__ out,
                       const float* __restrict__ gw,
                       const float* __restrict__ gb,
                       const float* __restrict__ gms) {
    const float invn = 1.0f / (float)NN;
    int stride = gridDim.x * blockDim.x;
    float4* o4 = (float4*)out;
    for (size_t i = blockIdx.x * blockDim.x + threadIdx.x; i < (size_t)NN * 32; i += stride) {
        int c4 = (int)(i & 31);
        float4 v = o4[i];
        #pragma unroll
        for (int j = 0; j < 4; j++) {
            int c = c4 * 4 + j;
            float mean = g_chs1[c] * invn;
            float m2   = g_chs2[c] * invn;
            float ms   = mean * __ldg(gms + c);
            float var  = m2 - 2.0f * ms * mean + ms * ms;
            float* pv = (&v.x) + j;
            *pv = __ldg(gw + c) * (*pv - ms) * rsqrtf(var + EPSV) + __ldg(gb + c);
        }
        o4[i] = v;
    }
}

// ---------------- launch ------------------------------------------------------
extern "C" void kernel_launch(void* const* d_in, const int* in_sizes, int n_in,
                              void* d_out, int out_size) {
    const float* x    = (const float*)d_in[0];
    const void*  ei   = d_in[1];
    const float* Wl   = (const float*)d_in[2];
    const float* Wr   = (const float*)d_in[3];
    const float* att  = (const float*)d_in[4];
    const float* bias = (const float*)d_in[5];
    const float* gw   = (const float*)d_in[6];
    const float* gb   = (const float*)d_in[7];
    const float* gms  = (const float*)d_in[8];
    float* out = (float*)d_out;

    k_detect<<<1, 32>>>(ei);
    k_zero<<<(NN + 255) / 256, 256>>>();
    k_gemm<<<GEMM_BLOCKS, 128>>>(x, Wl, Wr, ei);   // gemm + fused histogram

    k_scan1<<<SCAN_BLOCKS, 256>>>();
    k_scan2<<<1, 256>>>();
    k_scan3<<<SCAN_BLOCKS, 256>>>();

    int eblk4 = (ETOT + 1023) / 1024;
    k_scatter<<<eblk4, 256>>>(ei);

    int nblk = (NN * 32 + 255) / 256;  // warp per node
    k_edge<<<nblk, 256>>>(att, bias, out);

    k_norm<<<4096, 256>>>(out, gw, gb, gms);
}